// round 7
// baseline (speedup 1.0000x reference)
#include <cuda_runtime.h>

// Banded attention |i-j|<=4: B=256, S=128, D=1024, H=16, HD=64, fp32.
// One CTA per (b,h). NO smem staging: K and V are read directly via LDG.128
// (tiny per-CTA working set, L1D/L2-resident; each DRAM byte still read once).
// 8-lane subgroups handle adjacent query pairs over a shared 10-row window.
// Lane owns dims {4l..4l+3, 32+4l..32+4l+3} (two float4 chunks per row).
// Single-pass online softmax (scores O(+-6), raw exp safe), f32x2 packed FMA.

constexpr int S_LEN   = 128;
constexpr int D_MODEL = 1024;
constexpr int THREADS = 256;
constexpr int WROWS   = 10;

using u64 = unsigned long long;

__device__ __forceinline__ u64 f2_fma(u64 a, u64 b, u64 c) {
    u64 d; asm("fma.rn.f32x2 %0,%1,%2,%3;" : "=l"(d) : "l"(a), "l"(b), "l"(c)); return d;
}
__device__ __forceinline__ u64 f2_mul(u64 a, u64 b) {
    u64 d; asm("mul.rn.f32x2 %0,%1,%2;" : "=l"(d) : "l"(a), "l"(b)); return d;
}
__device__ __forceinline__ u64 f2_pack(float lo, float hi) {
    u64 d; asm("mov.b64 %0,{%1,%2};" : "=l"(d) : "f"(lo), "f"(hi)); return d;
}
__device__ __forceinline__ float2 f2_unpack(u64 a) {
    float lo, hi; asm("mov.b64 {%0,%1},%2;" : "=f"(lo), "=f"(hi) : "l"(a));
    return make_float2(lo, hi);
}
// Load float4 -> two packed f32x2 values.
__device__ __forceinline__ void ld4(const float* __restrict__ p, u64& a, u64& b) {
    float4 f = *reinterpret_cast<const float4*>(p);
    a = f2_pack(f.x, f.y);
    b = f2_pack(f.z, f.w);
}
__device__ __forceinline__ void st4(float* __restrict__ p, u64 a, u64 b) {
    float2 lo = f2_unpack(a), hi = f2_unpack(b);
    *reinterpret_cast<float4*>(p) = make_float4(lo.x, lo.y, hi.x, hi.y);
}

__global__ __launch_bounds__(THREADS, 4)
void band_attn_kernel(const float* __restrict__ q,
                      const float* __restrict__ k,
                      const float* __restrict__ v,
                      float* __restrict__ out)
{
    const int tid = threadIdx.x;
    const int bh  = blockIdx.x;
    const int b   = bh >> 4;
    const int h   = bh & 15;
    const size_t base = (size_t)b * S_LEN * D_MODEL + (size_t)h * 64;

    const float* kb = k   + base;
    const float* vb = v   + base;
    const float* qb = q   + base;
    float*       ob = out + base;

    const int warp = tid >> 5;
    const int lane = tid & 31;
    const int g    = lane >> 3;             // subgroup 0..3
    const int l    = lane & 7;              // lane in subgroup
    const int c0   = 4 * l;                 // first owned dim chunk
    const u64 scale2 = f2_pack(0.125f, 0.125f);

    #pragma unroll 1
    for (int t = 0; t < 2; ++t) {
        const int i0 = warp * 16 + t * 8 + g * 2;   // even query of the pair
        const int i1 = i0 + 1;

        // q chunks: [c0, c0+4) and [c0+32, c0+36), pre-scaled.
        u64 q0[4], q1[4];
        {
            const float* q0p = qb + (size_t)i0 * D_MODEL + c0;
            const float* q1p = qb + (size_t)i1 * D_MODEL + c0;
            ld4(q0p,      q0[0], q0[1]);
            ld4(q0p + 32, q0[2], q0[3]);
            ld4(q1p,      q1[0], q1[1]);
            ld4(q1p + 32, q1[2], q1[3]);
            #pragma unroll
            for (int kk = 0; kk < 4; ++kk) {
                q0[kk] = f2_mul(q0[kk], scale2);
                q1[kk] = f2_mul(q1[kk], scale2);
            }
        }

        float den0 = 0.f, den1 = 0.f;
        u64 acc0[4] = {0, 0, 0, 0};
        u64 acc1[4] = {0, 0, 0, 0};

        #pragma unroll
        for (int r = 0; r < WROWS; ++r) {
            const int j  = i0 - 4 + r;
            const int jc = min(max(j, 0), S_LEN - 1);

            u64 kv[4];
            {
                const float* krow = kb + (size_t)jc * D_MODEL + c0;
                ld4(krow,      kv[0], kv[1]);
                ld4(krow + 32, kv[2], kv[3]);
            }

            u64 a0 = f2_mul(q0[0], kv[0]);
            a0 = f2_fma(q0[1], kv[1], a0);
            a0 = f2_fma(q0[2], kv[2], a0);
            a0 = f2_fma(q0[3], kv[3], a0);
            u64 a1 = f2_mul(q1[0], kv[0]);
            a1 = f2_fma(q1[1], kv[1], a1);
            a1 = f2_fma(q1[2], kv[2], a1);
            a1 = f2_fma(q1[3], kv[3], a1);

            float2 s0 = f2_unpack(a0);
            float2 s1 = f2_unpack(a1);
            float p0 = s0.x + s0.y;
            float p1 = s1.x + s1.y;

            p0 += __shfl_xor_sync(0xffffffffu, p0, 1);
            p0 += __shfl_xor_sync(0xffffffffu, p0, 2);
            p0 += __shfl_xor_sync(0xffffffffu, p0, 4);
            p1 += __shfl_xor_sync(0xffffffffu, p1, 1);
            p1 += __shfl_xor_sync(0xffffffffu, p1, 2);
            p1 += __shfl_xor_sync(0xffffffffu, p1, 4);

            const bool in_seq = (j >= 0) && (j < S_LEN);
            const float e0 = (in_seq && r <= 8) ? __expf(p0) : 0.f;
            const float e1 = (in_seq && r >= 1) ? __expf(p1) : 0.f;
            den0 += e0;
            den1 += e1;

            u64 vv[4];
            {
                const float* vrow = vb + (size_t)jc * D_MODEL + c0;
                ld4(vrow,      vv[0], vv[1]);
                ld4(vrow + 32, vv[2], vv[3]);
            }
            const u64 e0p = f2_pack(e0, e0);
            const u64 e1p = f2_pack(e1, e1);
            #pragma unroll
            for (int kk = 0; kk < 4; ++kk) {
                acc0[kk] = f2_fma(e0p, vv[kk], acc0[kk]);
                acc1[kk] = f2_fma(e1p, vv[kk], acc1[kk]);
            }
        }

        const float inv0 = 1.0f / den0;
        const float inv1 = 1.0f / den1;
        const u64 i0p = f2_pack(inv0, inv0);
        const u64 i1p = f2_pack(inv1, inv1);
        float* o0 = ob + (size_t)i0 * D_MODEL + c0;
        float* o1 = ob + (size_t)i1 * D_MODEL + c0;
        st4(o0,      f2_mul(acc0[0], i0p), f2_mul(acc0[1], i0p));
        st4(o0 + 32, f2_mul(acc0[2], i0p), f2_mul(acc0[3], i0p));
        st4(o1,      f2_mul(acc1[0], i1p), f2_mul(acc1[1], i1p));
        st4(o1 + 32, f2_mul(acc1[2], i1p), f2_mul(acc1[3], i1p));
    }
}

extern "C" void kernel_launch(void* const* d_in, const int* in_sizes, int n_in,
                              void* d_out, int out_size)
{
    const float* q = (const float*)d_in[0];
    const float* k = (const float*)d_in[1];
    const float* v = (const float*)d_in[2];
    float* out = (float*)d_out;

    const int n_bh = 256 * 16;  // B * H
    band_attn_kernel<<<n_bh, THREADS>>>(q, k, v, out);
}

// round 8
// speedup vs baseline: 1.1638x; 1.1638x over previous
#include <cuda_runtime.h>

// Banded attention |i-j|<=4: B=256, S=128, D=1024, H=16, HD=64, fp32.
// One CTA per (b,h). K staged in smem (136 rows x 64 floats, 4 zero halo rows
// each end, no pad -- float4 quarter-warp reads are conflict-free); V read
// directly from global (L2/L1-resident). 8-lane subgroups handle adjacent
// query pairs over a shared 10-row window. Lane owns dims {4l..4l+3,
// 32+4l..32+4l+3} -> all K/V/Q/O accesses are .128. Single-pass online
// softmax (scores O(+-6)), packed f32x2 FMA. 4 CTAs/SM.

constexpr int S_LEN   = 128;
constexpr int D_MODEL = 1024;
constexpr int THREADS = 256;
constexpr int HALO    = 4;
constexpr int PROWS   = S_LEN + 2 * HALO;   // 136
constexpr int KSTRIDE = 64;                 // floats per smem row
constexpr int WROWS   = 10;

using u64 = unsigned long long;

__device__ __forceinline__ u64 f2_fma(u64 a, u64 b, u64 c) {
    u64 d; asm("fma.rn.f32x2 %0,%1,%2,%3;" : "=l"(d) : "l"(a), "l"(b), "l"(c)); return d;
}
__device__ __forceinline__ u64 f2_mul(u64 a, u64 b) {
    u64 d; asm("mul.rn.f32x2 %0,%1,%2;" : "=l"(d) : "l"(a), "l"(b)); return d;
}
__device__ __forceinline__ u64 f2_pack(float lo, float hi) {
    u64 d; asm("mov.b64 %0,{%1,%2};" : "=l"(d) : "f"(lo), "f"(hi)); return d;
}
__device__ __forceinline__ float2 f2_unpack(u64 a) {
    float lo, hi; asm("mov.b64 {%0,%1},%2;" : "=f"(lo), "=f"(hi) : "l"(a));
    return make_float2(lo, hi);
}
__device__ __forceinline__ void ld4(const float* __restrict__ p, u64& a, u64& b) {
    float4 f = *reinterpret_cast<const float4*>(p);
    a = f2_pack(f.x, f.y);
    b = f2_pack(f.z, f.w);
}
__device__ __forceinline__ void st4(float* __restrict__ p, u64 a, u64 b) {
    float2 lo = f2_unpack(a), hi = f2_unpack(b);
    *reinterpret_cast<float4*>(p) = make_float4(lo.x, lo.y, hi.x, hi.y);
}

__global__ __launch_bounds__(THREADS, 4)
void band_attn_kernel(const float* __restrict__ q,
                      const float* __restrict__ k,
                      const float* __restrict__ v,
                      float* __restrict__ out)
{
    extern __shared__ float smem[];
    float* ks = smem;                       // [136][64], row j+4

    const int tid = threadIdx.x;
    const int bh  = blockIdx.x;
    const int b   = bh >> 4;
    const int h   = bh & 15;
    const size_t base = (size_t)b * S_LEN * D_MODEL + (size_t)h * 64;

    const float* kb = k   + base;
    const float* vb = v   + base;
    const float* qb = q   + base;
    float*       ob = out + base;

    // Zero halo rows: 8 rows x 16 float4 = 128 stores.
    if (tid < 128) {
        int r4  = tid >> 4;                 // 0..7
        int c4  = tid & 15;
        int row = (r4 < HALO) ? r4 : (PROWS - 8 + r4);
        *reinterpret_cast<float4*>(ks + row * KSTRIDE + c4 * 4) =
            make_float4(0.f, 0.f, 0.f, 0.f);
    }

    // Stage K: 128 rows x 16 float4, fully coalesced both sides.
    #pragma unroll
    for (int it = 0; it < 8; ++it) {
        int idx = it * THREADS + tid;       // 0..2047
        int row = idx >> 4;
        int c4  = idx & 15;
        float4 kd = reinterpret_cast<const float4*>(kb + (size_t)row * D_MODEL)[c4];
        *reinterpret_cast<float4*>(ks + (row + HALO) * KSTRIDE + c4 * 4) = kd;
    }
    __syncthreads();

    const int warp = tid >> 5;
    const int lane = tid & 31;
    const int g    = lane >> 3;             // subgroup 0..3
    const int l    = lane & 7;              // lane in subgroup
    const int c0   = 4 * l;                 // owned chunk base
    const u64 scale2 = f2_pack(0.125f, 0.125f);

    #pragma unroll 1
    for (int t = 0; t < 2; ++t) {
        const int i0 = warp * 16 + t * 8 + g * 2;   // even query of the pair
        const int i1 = i0 + 1;

        u64 q0[4], q1[4];
        {
            const float* q0p = qb + (size_t)i0 * D_MODEL + c0;
            const float* q1p = qb + (size_t)i1 * D_MODEL + c0;
            ld4(q0p,      q0[0], q0[1]);
            ld4(q0p + 32, q0[2], q0[3]);
            ld4(q1p,      q1[0], q1[1]);
            ld4(q1p + 32, q1[2], q1[3]);
            #pragma unroll
            for (int kk = 0; kk < 4; ++kk) {
                q0[kk] = f2_mul(q0[kk], scale2);
                q1[kk] = f2_mul(q1[kk], scale2);
            }
        }

        float den0 = 0.f, den1 = 0.f;
        u64 acc0[4] = {0, 0, 0, 0};
        u64 acc1[4] = {0, 0, 0, 0};

        #pragma unroll
        for (int r = 0; r < WROWS; ++r) {
            const int j = i0 - HALO + r;

            u64 kv[4];
            {
                const float* krow = ks + (i0 + r) * KSTRIDE + c0;  // LDS.128 x2
                ld4(krow,      kv[0], kv[1]);
                ld4(krow + 32, kv[2], kv[3]);
            }

            u64 a0 = f2_mul(q0[0], kv[0]);
            a0 = f2_fma(q0[1], kv[1], a0);
            a0 = f2_fma(q0[2], kv[2], a0);
            a0 = f2_fma(q0[3], kv[3], a0);
            u64 a1 = f2_mul(q1[0], kv[0]);
            a1 = f2_fma(q1[1], kv[1], a1);
            a1 = f2_fma(q1[2], kv[2], a1);
            a1 = f2_fma(q1[3], kv[3], a1);

            float2 s0 = f2_unpack(a0);
            float2 s1 = f2_unpack(a1);
            float p0 = s0.x + s0.y;
            float p1 = s1.x + s1.y;

            p0 += __shfl_xor_sync(0xffffffffu, p0, 1);
            p0 += __shfl_xor_sync(0xffffffffu, p0, 2);
            p0 += __shfl_xor_sync(0xffffffffu, p0, 4);
            p1 += __shfl_xor_sync(0xffffffffu, p1, 1);
            p1 += __shfl_xor_sync(0xffffffffu, p1, 2);
            p1 += __shfl_xor_sync(0xffffffffu, p1, 4);

            const bool in_seq = (j >= 0) && (j < S_LEN);
            const float e0 = (in_seq && r <= 8) ? __expf(p0) : 0.f;
            const float e1 = (in_seq && r >= 1) ? __expf(p1) : 0.f;
            den0 += e0;
            den1 += e1;

            const int jc = min(max(j, 0), S_LEN - 1);
            u64 vv[4];
            {
                const float* vrow = vb + (size_t)jc * D_MODEL + c0;  // LDG.128 x2
                ld4(vrow,      vv[0], vv[1]);
                ld4(vrow + 32, vv[2], vv[3]);
            }
            const u64 e0p = f2_pack(e0, e0);
            const u64 e1p = f2_pack(e1, e1);
            #pragma unroll
            for (int kk = 0; kk < 4; ++kk) {
                acc0[kk] = f2_fma(e0p, vv[kk], acc0[kk]);
                acc1[kk] = f2_fma(e1p, vv[kk], acc1[kk]);
            }
        }

        const float inv0 = 1.0f / den0;
        const float inv1 = 1.0f / den1;
        const u64 i0p = f2_pack(inv0, inv0);
        const u64 i1p = f2_pack(inv1, inv1);
        float* o0 = ob + (size_t)i0 * D_MODEL + c0;
        float* o1 = ob + (size_t)i1 * D_MODEL + c0;
        st4(o0,      f2_mul(acc0[0], i0p), f2_mul(acc0[1], i0p));
        st4(o0 + 32, f2_mul(acc0[2], i0p), f2_mul(acc0[3], i0p));
        st4(o1,      f2_mul(acc1[0], i1p), f2_mul(acc1[1], i1p));
        st4(o1 + 32, f2_mul(acc1[2], i1p), f2_mul(acc1[3], i1p));
    }
}

extern "C" void kernel_launch(void* const* d_in, const int* in_sizes, int n_in,
                              void* d_out, int out_size)
{
    const float* q = (const float*)d_in[0];
    const float* k = (const float*)d_in[1];
    const float* v = (const float*)d_in[2];
    float* out = (float*)d_out;

    const int smem_bytes = PROWS * KSTRIDE * (int)sizeof(float);  // 34816
    cudaFuncSetAttribute(band_attn_kernel,
                         cudaFuncAttributeMaxDynamicSharedMemorySize, smem_bytes);

    const int n_bh = 256 * 16;  // B * H
    band_attn_kernel<<<n_bh, THREADS, smem_bytes>>>(q, k, v, out);
}

// round 9
// speedup vs baseline: 1.2129x; 1.0422x over previous
#include <cuda_runtime.h>

// Banded attention |i-j|<=4: B=256, S=128, D=1024, H=16, HD=64, fp32.
// Grid 8192: one CTA (128 thr) per (b,h,half) -> 64 queries. K window (72
// clamped rows, 18.4KB) staged via cp.async (reg-free, deep MLP); V read from
// global (L2-resident). 8 CTAs/SM in staggered stage/compute phases keeps
// DRAM continuously fed. Inner loop: 8-lane subgroups, adjacent query pairs,
// float4 lane ownership, packed f32x2 FMA, single-pass online softmax.

constexpr int S_LEN   = 128;
constexpr int D_MODEL = 1024;
constexpr int THREADS = 128;
constexpr int QB      = 64;        // queries per CTA
constexpr int KROWS   = QB + 8;    // 72 staged rows (clamped)
constexpr int WROWS   = 10;

using u64 = unsigned long long;

__device__ __forceinline__ u64 f2_fma(u64 a, u64 b, u64 c) {
    u64 d; asm("fma.rn.f32x2 %0,%1,%2,%3;" : "=l"(d) : "l"(a), "l"(b), "l"(c)); return d;
}
__device__ __forceinline__ u64 f2_mul(u64 a, u64 b) {
    u64 d; asm("mul.rn.f32x2 %0,%1,%2;" : "=l"(d) : "l"(a), "l"(b)); return d;
}
__device__ __forceinline__ u64 f2_pack(float lo, float hi) {
    u64 d; asm("mov.b64 %0,{%1,%2};" : "=l"(d) : "f"(lo), "f"(hi)); return d;
}
__device__ __forceinline__ float2 f2_unpack(u64 a) {
    float lo, hi; asm("mov.b64 {%0,%1},%2;" : "=f"(lo), "=f"(hi) : "l"(a));
    return make_float2(lo, hi);
}
__device__ __forceinline__ void ld4(const float* __restrict__ p, u64& a, u64& b) {
    float4 f = *reinterpret_cast<const float4*>(p);
    a = f2_pack(f.x, f.y);
    b = f2_pack(f.z, f.w);
}
__device__ __forceinline__ void st4(float* __restrict__ p, u64 a, u64 b) {
    float2 lo = f2_unpack(a), hi = f2_unpack(b);
    *reinterpret_cast<float4*>(p) = make_float4(lo.x, lo.y, hi.x, hi.y);
}
__device__ __forceinline__ void cp_async16(unsigned s, const void* g) {
    asm volatile("cp.async.ca.shared.global [%0], [%1], 16;" :: "r"(s), "l"(g));
}

__global__ __launch_bounds__(THREADS, 8)
void band_attn_kernel(const float* __restrict__ q,
                      const float* __restrict__ k,
                      const float* __restrict__ v,
                      float* __restrict__ out)
{
    extern __shared__ float smem[];   // K window [72][64]
    float* ks = smem;

    const int tid   = threadIdx.x;
    const int cta   = blockIdx.x;     // 0..8191
    const int bh    = cta >> 1;
    const int half  = cta & 1;
    const int qbase = half * QB;
    const int b     = bh >> 4;
    const int h     = bh & 15;
    const size_t base = (size_t)b * S_LEN * D_MODEL + (size_t)h * 64;

    const float* kb = k   + base;
    const float* vb = v   + base;
    const float* qb = q   + base;
    float*       ob = out + base;

    // Stage K window via cp.async: smem row r holds K[clamp(qbase-4+r)].
    // 72 rows x 16 float4 = 1152 chunks; 9 per thread; zero reg payload.
    const unsigned ks_s = (unsigned)__cvta_generic_to_shared(ks);
    #pragma unroll
    for (int it = 0; it < 9; ++it) {
        int idx = it * THREADS + tid;       // 0..1151
        int row = idx >> 4;
        int c4  = idx & 15;
        int gr  = min(max(qbase - 4 + row, 0), S_LEN - 1);
        cp_async16(ks_s + (unsigned)(row * 64 + c4 * 4) * 4u,
                   kb + (size_t)gr * D_MODEL + c4 * 4);
    }
    asm volatile("cp.async.commit_group;");

    const int warp = tid >> 5;              // 0..3
    const int lane = tid & 31;
    const int g    = lane >> 3;             // subgroup 0..3
    const int l    = lane & 7;
    const int c0   = 4 * l;
    const u64 scale2 = f2_pack(0.125f, 0.125f);

    // Hoist t=0 Q loads: these LDGs fly while the K stage is in-flight.
    u64 q0[4], q1[4];
    {
        const int i0 = qbase + warp * 16 + g * 2;
        const float* q0p = qb + (size_t)i0 * D_MODEL + c0;
        const float* q1p = qb + (size_t)(i0 + 1) * D_MODEL + c0;
        ld4(q0p,      q0[0], q0[1]);
        ld4(q0p + 32, q0[2], q0[3]);
        ld4(q1p,      q1[0], q1[1]);
        ld4(q1p + 32, q1[2], q1[3]);
        #pragma unroll
        for (int kk = 0; kk < 4; ++kk) {
            q0[kk] = f2_mul(q0[kk], scale2);
            q1[kk] = f2_mul(q1[kk], scale2);
        }
    }

    asm volatile("cp.async.wait_group 0;");
    __syncthreads();

    #pragma unroll 1
    for (int t = 0; t < 2; ++t) {
        const int il = warp * 16 + t * 8 + g * 2;   // CTA-local even query
        const int i0 = qbase + il;
        const int i1 = i0 + 1;

        if (t == 1) {
            const float* q0p = qb + (size_t)i0 * D_MODEL + c0;
            const float* q1p = qb + (size_t)i1 * D_MODEL + c0;
            ld4(q0p,      q0[0], q0[1]);
            ld4(q0p + 32, q0[2], q0[3]);
            ld4(q1p,      q1[0], q1[1]);
            ld4(q1p + 32, q1[2], q1[3]);
            #pragma unroll
            for (int kk = 0; kk < 4; ++kk) {
                q0[kk] = f2_mul(q0[kk], scale2);
                q1[kk] = f2_mul(q1[kk], scale2);
            }
        }

        float den0 = 0.f, den1 = 0.f;
        u64 acc0[4] = {0, 0, 0, 0};
        u64 acc1[4] = {0, 0, 0, 0};

        #pragma unroll
        for (int r = 0; r < WROWS; ++r) {
            const int j = i0 - 4 + r;

            u64 kv[4];
            {
                // smem row (il + r) holds K[clamp(i0-4+r)] exactly.
                const float* krow = ks + (il + r) * 64 + c0;
                ld4(krow,      kv[0], kv[1]);
                ld4(krow + 32, kv[2], kv[3]);
            }

            u64 a0 = f2_mul(q0[0], kv[0]);
            a0 = f2_fma(q0[1], kv[1], a0);
            a0 = f2_fma(q0[2], kv[2], a0);
            a0 = f2_fma(q0[3], kv[3], a0);
            u64 a1 = f2_mul(q1[0], kv[0]);
            a1 = f2_fma(q1[1], kv[1], a1);
            a1 = f2_fma(q1[2], kv[2], a1);
            a1 = f2_fma(q1[3], kv[3], a1);

            float2 s0 = f2_unpack(a0);
            float2 s1 = f2_unpack(a1);
            float p0 = s0.x + s0.y;
            float p1 = s1.x + s1.y;

            p0 += __shfl_xor_sync(0xffffffffu, p0, 1);
            p0 += __shfl_xor_sync(0xffffffffu, p0, 2);
            p0 += __shfl_xor_sync(0xffffffffu, p0, 4);
            p1 += __shfl_xor_sync(0xffffffffu, p1, 1);
            p1 += __shfl_xor_sync(0xffffffffu, p1, 2);
            p1 += __shfl_xor_sync(0xffffffffu, p1, 4);

            const bool in_seq = (j >= 0) && (j < S_LEN);
            const float e0 = (in_seq && r <= 8) ? __expf(p0) : 0.f;
            const float e1 = (in_seq && r >= 1) ? __expf(p1) : 0.f;
            den0 += e0;
            den1 += e1;

            const int jc = min(max(j, 0), S_LEN - 1);
            u64 vv[4];
            {
                const float* vrow = vb + (size_t)jc * D_MODEL + c0;
                ld4(vrow,      vv[0], vv[1]);
                ld4(vrow + 32, vv[2], vv[3]);
            }
            const u64 e0p = f2_pack(e0, e0);
            const u64 e1p = f2_pack(e1, e1);
            #pragma unroll
            for (int kk = 0; kk < 4; ++kk) {
                acc0[kk] = f2_fma(e0p, vv[kk], acc0[kk]);
                acc1[kk] = f2_fma(e1p, vv[kk], acc1[kk]);
            }
        }

        const float inv0 = 1.0f / den0;
        const float inv1 = 1.0f / den1;
        const u64 i0p = f2_pack(inv0, inv0);
        const u64 i1p = f2_pack(inv1, inv1);
        float* o0 = ob + (size_t)i0 * D_MODEL + c0;
        float* o1 = ob + (size_t)i1 * D_MODEL + c0;
        st4(o0,      f2_mul(acc0[0], i0p), f2_mul(acc0[1], i0p));
        st4(o0 + 32, f2_mul(acc0[2], i0p), f2_mul(acc0[3], i0p));
        st4(o1,      f2_mul(acc1[0], i1p), f2_mul(acc1[1], i1p));
        st4(o1 + 32, f2_mul(acc1[2], i1p), f2_mul(acc1[3], i1p));
    }
}

extern "C" void kernel_launch(void* const* d_in, const int* in_sizes, int n_in,
                              void* d_out, int out_size)
{
    const float* q = (const float*)d_in[0];
    const float* k = (const float*)d_in[1];
    const float* v = (const float*)d_in[2];
    float* out = (float*)d_out;

    const int smem_bytes = KROWS * 64 * (int)sizeof(float);  // 18432
    cudaFuncSetAttribute(band_attn_kernel,
                         cudaFuncAttributeMaxDynamicSharedMemorySize, smem_bytes);

    const int n_cta = 256 * 16 * 2;  // B * H * 2 halves
    band_attn_kernel<<<n_cta, THREADS, smem_bytes>>>(q, k, v, out);
}